// round 9
// baseline (speedup 1.0000x reference)
#include <cuda_runtime.h>
#include <math.h>

#define Nn 19
#define PADA 21      // eig kernel pad (conflict-free: gcd(21,32)=1)
#define PADB 20      // dense kernel An pad
#define KE 16
#define Dd 64
#define Tt 1024
#define Bb 16
#define Gg (Bb*Tt)   // 16384 graphs
#define NSWEEP 5
#define ALPHA_C 0.05f
#define HOPC 0.475f  // (1-alpha)/K
#define LN_EPS 1e-5f

// scratch (allocation-free rule: __device__ globals)
__device__ float g_anorm[(size_t)Gg*Nn*Nn];   // ~23.7 MB
__device__ float g_pe[(size_t)Gg*Nn*KE];      // ~19.9 MB

__device__ __forceinline__ float softplusf(float x){
    return fmaxf(x, 0.0f) + log1pf(expf(-fabsf(x)));
}

// ---------------------------------------------------------------------------
// Kernel A: per-graph (one warp each): a_norm + symmetrized Laplacian +
// Jacobi eigensolver (tournament ordering) + PE extraction.
// ---------------------------------------------------------------------------
__global__ void __launch_bounds__(256) eig_kernel(
    const float* __restrict__ adjacency,
    const float* __restrict__ edge_w_p,
    const float* __restrict__ edge_b_p)
{
    __shared__ float smem[8*(2*Nn*PADA + 96)];
    const int w = threadIdx.x >> 5;
    const int l = threadIdx.x & 31;
    const int g = blockIdx.x*8 + w;

    float* M   = smem + w*(2*Nn*PADA + 96);   // adj -> identity -> EVEC
    float* V   = M + Nn*PADA;                 // w -> lapS -> diagonalized
    float* AUX = V + Nn*PADA;
    float* CS  = AUX;                         // 9 cosines
    float* SS  = AUX + 9;                     // 9 sines
    float* DIS = AUX + 18;                    // 19
    int*   ORD = (int*)(AUX + 40);            // 16
    float* SGN = AUX + 56;                    // 16

    const float ew = edge_w_p[0];
    const float eb = edge_b_p[0];
    const float* adj = adjacency + (size_t)g*Nn*Nn;

    for (int i = l; i < Nn*Nn; i += 32)
        M[(i/Nn)*PADA + (i%Nn)] = adj[i];
    __syncwarp();

    for (int i = l; i < Nn*Nn; i += 32){
        int r = i/Nn, c = i%Nn;
        float a = M[r*PADA + c];
        V[r*PADA + c] = (a > 0.0f) ? softplusf(a*ew + eb) : 0.0f;
    }
    __syncwarp();
    if (l < Nn){
        if (!(M[l*PADA + l] > 0.0f)) V[l*PADA + l] += 1.0f;
    }
    __syncwarp();

    if (l < Nn){
        float dsum = 0.0f;
        #pragma unroll
        for (int i = 0; i < Nn; i++) dsum += V[i*PADA + l];
        DIS[l] = (dsum > 0.0f) ? rsqrtf(fmaxf(dsum, 1e-30f)) : 0.0f;
    }
    __syncwarp();

    {
        float* ga = g_anorm + (size_t)g*Nn*Nn;
        for (int i = l; i < Nn*Nn; i += 32){
            int r = i/Nn, c = i%Nn;
            ga[i] = DIS[r]*V[r*PADA + c]*DIS[c];
        }
    }
    __syncwarp();

    if (l < Nn){
        float dsum = 0.0f;
        #pragma unroll
        for (int j = 0; j < Nn; j++) dsum += M[l*PADA + j];
        DIS[l] = rsqrtf(fmaxf(dsum, 1e-6f));
    }
    __syncwarp();

    for (int i = l; i < Nn*Nn; i += 32){
        int r = i/Nn, c = i%Nn;
        float an = 0.5f * DIS[r]*DIS[c] * (M[r*PADA + c] + M[c*PADA + r]);
        V[r*PADA + c] = ((r == c) ? (1.0f + 1e-5f) : 0.0f) - an;
    }
    __syncwarp();

    for (int i = l; i < Nn*Nn; i += 32){
        int r = i/Nn, c = i%Nn;
        M[r*PADA + c] = (r == c) ? 1.0f : 0.0f;
    }
    __syncwarp();

    // per-lane round-invariant task descriptors
    float* cBase[11];
    int    cK[11];
    bool   cValid[11];
    #pragma unroll
    for (int it = 0; it < 11; ++it){
        int t0 = l + 32*it;
        cValid[it] = (t0 < 2*9*Nn);
        int tt = cValid[it] ? t0 : 0;
        int m = tt / (9*Nn);
        int u = tt % (9*Nn);
        cK[it]    = u / Nn + 1;
        cBase[it] = (m ? M : V) + (u % Nn)*PADA;
    }
    int  rK[6], rJ[6];
    bool rValid[6];
    #pragma unroll
    for (int it = 0; it < 6; ++it){
        int t0 = l + 32*it;
        rValid[it] = (t0 < 9*Nn);
        int tt = rValid[it] ? t0 : 0;
        rK[it] = tt / Nn + 1;
        rJ[it] = tt % Nn;
    }

    for (int sweep = 0; sweep < NSWEEP; ++sweep){
        for (int r = 0; r < Nn; r++){
            if (l >= 1 && l <= 9){
                int k = l;
                int p = r + k; if (p >= Nn) p -= Nn;
                int q = r - k; if (q < 0)  q += Nn;
                float app = V[p*PADA + p];
                float aqq = V[q*PADA + q];
                float apq = V[p*PADA + q];
                float c = 1.0f, s = 0.0f;
                if (fabsf(apq) > 1e-30f){
                    float tau = (aqq - app) / (2.0f*apq);
                    float t = 1.0f / (fabsf(tau) + sqrtf(1.0f + tau*tau));
                    if (tau < 0.0f) t = -t;
                    c = rsqrtf(1.0f + t*t);
                    s = t*c;
                }
                CS[k-1] = c; SS[k-1] = s;
            }
            __syncwarp();
            #pragma unroll
            for (int it = 0; it < 11; ++it){
                if (cValid[it]){
                    int k = cK[it];
                    int p = r + k; if (p >= Nn) p -= Nn;
                    int q = r - k; if (q < 0)  q += Nn;
                    float c = CS[k-1], s = SS[k-1];
                    float* base = cBase[it];
                    float vp = base[p];
                    float vq = base[q];
                    base[p] = c*vp - s*vq;
                    base[q] = s*vp + c*vq;
                }
            }
            __syncwarp();
            #pragma unroll
            for (int it = 0; it < 6; ++it){
                if (rValid[it]){
                    int k = rK[it], j = rJ[it];
                    int p = r + k; if (p >= Nn) p -= Nn;
                    int q = r - k; if (q < 0)  q += Nn;
                    float c = CS[k-1], s = SS[k-1];
                    float vp = V[p*PADA + j];
                    float vq = V[q*PADA + j];
                    V[p*PADA + j] = c*vp - s*vq;
                    V[q*PADA + j] = s*vp + c*vq;
                }
            }
            __syncwarp();
        }
    }

    if (l < Nn){
        float dv = V[l*PADA + l];
        int rank = 0;
        #pragma unroll
        for (int j = 0; j < Nn; j++){
            float dj = V[j*PADA + j];
            rank += (dj < dv) || (dj == dv && j < l);
        }
        if (rank < KE) ORD[rank] = l;
    }
    __syncwarp();
    if (l < KE){
        int i = ORD[l];
        float sum = 0.0f;
        #pragma unroll
        for (int n = 0; n < Nn; n++) sum += M[n*PADA + i];
        SGN[l] = (sum > 0.0f) ? 1.0f : ((sum < 0.0f) ? -1.0f : 1.0f);
    }
    __syncwarp();
    {
        float* gp = g_pe + (size_t)g*Nn*KE;
        for (int t0 = l; t0 < Nn*KE; t0 += 32){
            int n = t0 / KE, m = t0 % KE;
            float v = M[n*PADA + ORD[m]] * SGN[m];
            if (isnan(v)) v = 0.0f;
            else if (isinf(v)) v = (v > 0.0f) ? 1.0f : -1.0f;
            gp[t0] = v;
        }
    }
}

// ---------------------------------------------------------------------------
// Kernel B (rewritten): 2 graphs per 128-thread CTA; 64 threads per graph;
// each thread owns one feature column d in registers end-to-end.
// Propagation is column-local -> both hops + combine stay in registers.
// LN via shfl butterflies + tiny 2-warp shared combine (no bank conflicts).
// ---------------------------------------------------------------------------
__global__ void __launch_bounds__(128) dense_kernel(
    const float* __restrict__ features,
    const float* __restrict__ W0, const float* __restrict__ b0,
    const float* __restrict__ W1, const float* __restrict__ b1,
    const float* __restrict__ ln0g, const float* __restrict__ ln0b,
    const float* __restrict__ ln1g, const float* __restrict__ ln1b,
    float* __restrict__ out)
{
    __shared__ float An[2][Nn*PADB];      // 2 x 380
    __shared__ float XC[2][Nn*80];        // 2 x 1520 (x | pe)
    __shared__ float Y [2][Nn*64];        // LN0 output for GEMM1
    __shared__ float RED[2][2][2][Nn];    // [graph][warp][stat][n]

    const int tid  = threadIdx.x;
    const int sub  = tid >> 6;            // graph within CTA
    const int d    = tid & 63;            // feature column
    const int wg   = (tid >> 5) & 1;      // warp within graph
    const int lane = tid & 31;
    const int g0   = blockIdx.x*2;
    const int g    = g0 + sub;
    const int b    = g >> 10;
    const int t    = g & 1023;

    // cooperative loads
    for (int i = tid; i < 2*Nn*Nn; i += 128){
        int s = i / (Nn*Nn), u = i % (Nn*Nn);
        An[s][(u/Nn)*PADB + (u%Nn)] = g_anorm[(size_t)(g0+s)*Nn*Nn + u];
    }
    for (int i = tid; i < 2*Nn*64; i += 128){
        int s = i / (Nn*64), u = i % (Nn*64);
        int n = u >> 6, dd = u & 63;
        int gs = g0 + s;
        XC[s][n*80 + dd] =
            features[((size_t)(((gs>>10)*Nn + n)*Tt + (gs&1023)))*64 + dd];
    }
    for (int i = tid; i < 2*Nn*KE; i += 128){
        int s = i / (Nn*KE), u = i % (Nn*KE);
        int n = u / KE, m = u % KE;
        XC[s][n*80 + 64 + m] = g_pe[(size_t)(g0+s)*Nn*KE + u];
    }
    __syncthreads();

    float z[Nn], z1[Nn], h[Nn], y0[Nn];

    // ---- GEMM0: z[n] = XC[n,:] . W0[d,:]  (W0 is (64,80) row-major) ----
    {
        float wreg[80];
        #pragma unroll
        for (int f4 = 0; f4 < 20; f4++){
            float4 v = *reinterpret_cast<const float4*>(W0 + d*80 + f4*4);
            wreg[f4*4+0] = v.x; wreg[f4*4+1] = v.y;
            wreg[f4*4+2] = v.z; wreg[f4*4+3] = v.w;
        }
        #pragma unroll
        for (int n = 0; n < Nn; n++){
            const float4* xr = reinterpret_cast<const float4*>(XC[sub] + n*80);
            float acc = 0.0f;
            #pragma unroll
            for (int f4 = 0; f4 < 20; f4++){
                float4 x = xr[f4];
                acc += x.x*wreg[f4*4+0] + x.y*wreg[f4*4+1]
                     + x.z*wreg[f4*4+2] + x.w*wreg[f4*4+3];
            }
            z[n] = acc;
        }
    }

    // ---- hops (register-local): z1 = A^T z ; h = a*z + C*(z1 + A^T z1) + b0 ----
    #pragma unroll
    for (int n = 0; n < Nn; n++){
        float acc = 0.0f;
        #pragma unroll
        for (int i = 0; i < Nn; i++) acc += An[sub][i*PADB + n]*z[i];
        z1[n] = acc;
    }
    {
        float bb = __ldg(b0 + d);
        #pragma unroll
        for (int n = 0; n < Nn; n++){
            float acc = 0.0f;
            #pragma unroll
            for (int i = 0; i < Nn; i++) acc += An[sub][i*PADB + n]*z1[i];
            h[n] = ALPHA_C*z[n] + HOPC*(z1[n] + acc) + bb;
        }
    }

    // ---- LN0: per-n stats over 64 threads (shfl butterfly + 2-warp combine) ----
    {
        float aa[Nn], bb2[Nn];
        #pragma unroll
        for (int n = 0; n < Nn; n++){ aa[n] = h[n]; bb2[n] = h[n]*h[n]; }
        #pragma unroll
        for (int off = 16; off >= 1; off >>= 1){
            #pragma unroll
            for (int n = 0; n < Nn; n++){
                aa[n]  += __shfl_xor_sync(0xffffffffu, aa[n],  off);
                bb2[n] += __shfl_xor_sync(0xffffffffu, bb2[n], off);
            }
        }
        if (lane == 0){
            #pragma unroll
            for (int n = 0; n < Nn; n++){
                RED[sub][wg][0][n] = aa[n];
                RED[sub][wg][1][n] = bb2[n];
            }
        }
    }
    __syncthreads();
    {
        float gg = __ldg(ln0g + d), bbb = __ldg(ln0b + d);
        #pragma unroll
        for (int n = 0; n < Nn; n++){
            float s = RED[sub][0][0][n] + RED[sub][1][0][n];
            float q = RED[sub][0][1][n] + RED[sub][1][1][n];
            float mu = s * (1.0f/64.0f);
            float var = q * (1.0f/64.0f) - mu*mu;
            float rs = rsqrtf(fmaxf(var, 0.0f) + LN_EPS);
            float yv = (h[n] - mu)*rs;
            y0[n] = yv*gg + bbb;
            Y[sub][n*64 + d] = y0[n];
        }
    }
    __syncthreads();

    // ---- GEMM1: z[n] = Y[n,:] . W1[d,:]  (W1 is (64,64)) ----
    {
        float wreg[64];
        #pragma unroll
        for (int f4 = 0; f4 < 16; f4++){
            float4 v = *reinterpret_cast<const float4*>(W1 + d*64 + f4*4);
            wreg[f4*4+0] = v.x; wreg[f4*4+1] = v.y;
            wreg[f4*4+2] = v.z; wreg[f4*4+3] = v.w;
        }
        #pragma unroll
        for (int n = 0; n < Nn; n++){
            const float4* xr = reinterpret_cast<const float4*>(Y[sub] + n*64);
            float acc = 0.0f;
            #pragma unroll
            for (int f4 = 0; f4 < 16; f4++){
                float4 x = xr[f4];
                acc += x.x*wreg[f4*4+0] + x.y*wreg[f4*4+1]
                     + x.z*wreg[f4*4+2] + x.w*wreg[f4*4+3];
            }
            z[n] = acc;
        }
    }

    // ---- hops + residual: h = a*z + C*(z1 + A^T z1) + b1 + y0 ----
    #pragma unroll
    for (int n = 0; n < Nn; n++){
        float acc = 0.0f;
        #pragma unroll
        for (int i = 0; i < Nn; i++) acc += An[sub][i*PADB + n]*z[i];
        z1[n] = acc;
    }
    {
        float bb = __ldg(b1 + d);
        #pragma unroll
        for (int n = 0; n < Nn; n++){
            float acc = 0.0f;
            #pragma unroll
            for (int i = 0; i < Nn; i++) acc += An[sub][i*PADB + n]*z1[i];
            h[n] = ALPHA_C*z[n] + HOPC*(z1[n] + acc) + bb + y0[n];
        }
    }

    // ---- LN1 + store ----
    {
        float aa[Nn], bb2[Nn];
        #pragma unroll
        for (int n = 0; n < Nn; n++){ aa[n] = h[n]; bb2[n] = h[n]*h[n]; }
        #pragma unroll
        for (int off = 16; off >= 1; off >>= 1){
            #pragma unroll
            for (int n = 0; n < Nn; n++){
                aa[n]  += __shfl_xor_sync(0xffffffffu, aa[n],  off);
                bb2[n] += __shfl_xor_sync(0xffffffffu, bb2[n], off);
            }
        }
        if (lane == 0){
            #pragma unroll
            for (int n = 0; n < Nn; n++){
                RED[sub][wg][0][n] = aa[n];
                RED[sub][wg][1][n] = bb2[n];
            }
        }
    }
    __syncthreads();
    {
        float gg = __ldg(ln1g + d), bbb = __ldg(ln1b + d);
        #pragma unroll
        for (int n = 0; n < Nn; n++){
            float s = RED[sub][0][0][n] + RED[sub][1][0][n];
            float q = RED[sub][0][1][n] + RED[sub][1][1][n];
            float mu = s * (1.0f/64.0f);
            float var = q * (1.0f/64.0f) - mu*mu;
            float rs = rsqrtf(fmaxf(var, 0.0f) + LN_EPS);
            float v = (h[n] - mu)*rs*gg + bbb;
            out[((size_t)((b*Nn + n)*Tt + t))*64 + d] = v;
        }
    }
}

// ---------------------------------------------------------------------------
extern "C" void kernel_launch(void* const* d_in, const int* in_sizes, int n_in,
                              void* d_out, int out_size)
{
    const float* features  = (const float*)d_in[0];
    const float* adjacency = (const float*)d_in[1];
    const float* edge_w    = (const float*)d_in[2];
    const float* edge_b    = (const float*)d_in[3];
    const float* gnn0_W    = (const float*)d_in[4];
    const float* gnn0_b    = (const float*)d_in[5];
    const float* gnn1_W    = (const float*)d_in[6];
    const float* gnn1_b    = (const float*)d_in[7];
    const float* ln0_g     = (const float*)d_in[8];
    const float* ln0_b     = (const float*)d_in[9];
    const float* ln1_g     = (const float*)d_in[10];
    const float* ln1_b     = (const float*)d_in[11];
    float* out = (float*)d_out;

    eig_kernel<<<Gg/8, 256>>>(adjacency, edge_w, edge_b);
    dense_kernel<<<Gg/2, 128>>>(features, gnn0_W, gnn0_b, gnn1_W, gnn1_b,
                                ln0_g, ln0_b, ln1_g, ln1_b, out);
}

// round 10
// speedup vs baseline: 1.0335x; 1.0335x over previous
#include <cuda_runtime.h>
#include <math.h>

#define Nn 19
#define PADA 21      // eig kernel pad (conflict-free: gcd(21,32)=1)
#define PADB 20      // dense kernel An pad
#define KE 16
#define Dd 64
#define Tt 1024
#define Bb 16
#define Gg (Bb*Tt)   // 16384 graphs
#define NSWEEP 5
#define ALPHA_C 0.05f
#define HOPC 0.475f  // (1-alpha)/K
#define LN_EPS 1e-5f

// scratch (allocation-free rule: __device__ globals)
__device__ float g_anorm[(size_t)Gg*Nn*Nn];   // ~23.7 MB
__device__ float g_pe[(size_t)Gg*Nn*KE];      // ~19.9 MB

__device__ __forceinline__ float softplusf(float x){
    return fmaxf(x, 0.0f) + log1pf(expf(-fabsf(x)));
}

// ---------------------------------------------------------------------------
// Kernel A: per-graph (one warp each): a_norm + symmetrized Laplacian +
// Jacobi eigensolver (tournament ordering) + PE extraction.
// ---------------------------------------------------------------------------
__global__ void __launch_bounds__(256) eig_kernel(
    const float* __restrict__ adjacency,
    const float* __restrict__ edge_w_p,
    const float* __restrict__ edge_b_p)
{
    __shared__ float smem[8*(2*Nn*PADA + 96)];
    const int w = threadIdx.x >> 5;
    const int l = threadIdx.x & 31;
    const int g = blockIdx.x*8 + w;

    float* M   = smem + w*(2*Nn*PADA + 96);   // adj -> identity -> EVEC
    float* V   = M + Nn*PADA;                 // w -> lapS -> diagonalized
    float* AUX = V + Nn*PADA;
    float* CS  = AUX;                         // 9 cosines
    float* SS  = AUX + 9;                     // 9 sines
    float* DIS = AUX + 18;                    // 19
    int*   ORD = (int*)(AUX + 40);            // 16
    float* SGN = AUX + 56;                    // 16

    const float ew = edge_w_p[0];
    const float eb = edge_b_p[0];
    const float* adj = adjacency + (size_t)g*Nn*Nn;

    for (int i = l; i < Nn*Nn; i += 32)
        M[(i/Nn)*PADA + (i%Nn)] = adj[i];
    __syncwarp();

    for (int i = l; i < Nn*Nn; i += 32){
        int r = i/Nn, c = i%Nn;
        float a = M[r*PADA + c];
        V[r*PADA + c] = (a > 0.0f) ? softplusf(a*ew + eb) : 0.0f;
    }
    __syncwarp();
    if (l < Nn){
        if (!(M[l*PADA + l] > 0.0f)) V[l*PADA + l] += 1.0f;
    }
    __syncwarp();

    if (l < Nn){
        float dsum = 0.0f;
        #pragma unroll
        for (int i = 0; i < Nn; i++) dsum += V[i*PADA + l];
        DIS[l] = (dsum > 0.0f) ? rsqrtf(fmaxf(dsum, 1e-30f)) : 0.0f;
    }
    __syncwarp();

    {
        float* ga = g_anorm + (size_t)g*Nn*Nn;
        for (int i = l; i < Nn*Nn; i += 32){
            int r = i/Nn, c = i%Nn;
            ga[i] = DIS[r]*V[r*PADA + c]*DIS[c];
        }
    }
    __syncwarp();

    if (l < Nn){
        float dsum = 0.0f;
        #pragma unroll
        for (int j = 0; j < Nn; j++) dsum += M[l*PADA + j];
        DIS[l] = rsqrtf(fmaxf(dsum, 1e-6f));
    }
    __syncwarp();

    for (int i = l; i < Nn*Nn; i += 32){
        int r = i/Nn, c = i%Nn;
        float an = 0.5f * DIS[r]*DIS[c] * (M[r*PADA + c] + M[c*PADA + r]);
        V[r*PADA + c] = ((r == c) ? (1.0f + 1e-5f) : 0.0f) - an;
    }
    __syncwarp();

    for (int i = l; i < Nn*Nn; i += 32){
        int r = i/Nn, c = i%Nn;
        M[r*PADA + c] = (r == c) ? 1.0f : 0.0f;
    }
    __syncwarp();

    // per-lane round-invariant task descriptors
    float* cBase[11];
    int    cK[11];
    bool   cValid[11];
    #pragma unroll
    for (int it = 0; it < 11; ++it){
        int t0 = l + 32*it;
        cValid[it] = (t0 < 2*9*Nn);
        int tt = cValid[it] ? t0 : 0;
        int m = tt / (9*Nn);
        int u = tt % (9*Nn);
        cK[it]    = u / Nn + 1;
        cBase[it] = (m ? M : V) + (u % Nn)*PADA;
    }
    int  rK[6], rJ[6];
    bool rValid[6];
    #pragma unroll
    for (int it = 0; it < 6; ++it){
        int t0 = l + 32*it;
        rValid[it] = (t0 < 9*Nn);
        int tt = rValid[it] ? t0 : 0;
        rK[it] = tt / Nn + 1;
        rJ[it] = tt % Nn;
    }

    for (int sweep = 0; sweep < NSWEEP; ++sweep){
        for (int r = 0; r < Nn; r++){
            if (l >= 1 && l <= 9){
                int k = l;
                int p = r + k; if (p >= Nn) p -= Nn;
                int q = r - k; if (q < 0)  q += Nn;
                float app = V[p*PADA + p];
                float aqq = V[q*PADA + q];
                float apq = V[p*PADA + q];
                float c = 1.0f, s = 0.0f;
                if (fabsf(apq) > 1e-30f){
                    float tau = (aqq - app) / (2.0f*apq);
                    float t = 1.0f / (fabsf(tau) + sqrtf(1.0f + tau*tau));
                    if (tau < 0.0f) t = -t;
                    c = rsqrtf(1.0f + t*t);
                    s = t*c;
                }
                CS[k-1] = c; SS[k-1] = s;
            }
            __syncwarp();
            #pragma unroll
            for (int it = 0; it < 11; ++it){
                if (cValid[it]){
                    int k = cK[it];
                    int p = r + k; if (p >= Nn) p -= Nn;
                    int q = r - k; if (q < 0)  q += Nn;
                    float c = CS[k-1], s = SS[k-1];
                    float* base = cBase[it];
                    float vp = base[p];
                    float vq = base[q];
                    base[p] = c*vp - s*vq;
                    base[q] = s*vp + c*vq;
                }
            }
            __syncwarp();
            #pragma unroll
            for (int it = 0; it < 6; ++it){
                if (rValid[it]){
                    int k = rK[it], j = rJ[it];
                    int p = r + k; if (p >= Nn) p -= Nn;
                    int q = r - k; if (q < 0)  q += Nn;
                    float c = CS[k-1], s = SS[k-1];
                    float vp = V[p*PADA + j];
                    float vq = V[q*PADA + j];
                    V[p*PADA + j] = c*vp - s*vq;
                    V[q*PADA + j] = s*vp + c*vq;
                }
            }
            __syncwarp();
        }
    }

    if (l < Nn){
        float dv = V[l*PADA + l];
        int rank = 0;
        #pragma unroll
        for (int j = 0; j < Nn; j++){
            float dj = V[j*PADA + j];
            rank += (dj < dv) || (dj == dv && j < l);
        }
        if (rank < KE) ORD[rank] = l;
    }
    __syncwarp();
    if (l < KE){
        int i = ORD[l];
        float sum = 0.0f;
        #pragma unroll
        for (int n = 0; n < Nn; n++) sum += M[n*PADA + i];
        SGN[l] = (sum > 0.0f) ? 1.0f : ((sum < 0.0f) ? -1.0f : 1.0f);
    }
    __syncwarp();
    {
        float* gp = g_pe + (size_t)g*Nn*KE;
        for (int t0 = l; t0 < Nn*KE; t0 += 32){
            int n = t0 / KE, m = t0 % KE;
            float v = M[n*PADA + ORD[m]] * SGN[m];
            if (isnan(v)) v = 0.0f;
            else if (isinf(v)) v = (v > 0.0f) ? 1.0f : -1.0f;
            gp[t0] = v;
        }
    }
}

// ---------------------------------------------------------------------------
// Kernel B: CTA-per-graph fused SSGConv0 -> LN0 -> SSGConv1 + res -> LN1.
// R7 structure (shared-resident Z, 96 regs, occ ~31%) with conflict-free
// shfl-butterfly LayerNorm stats (the only change vs R7).
// Thread layout: tid -> (half = tid/64 selects node range, d = tid%64).
// Warps 0,1 serve half 0 (nodes 0..9); warps 2,3 serve half 1 (nodes 10..18).
// ---------------------------------------------------------------------------
__global__ void __launch_bounds__(128) dense_kernel(
    const float* __restrict__ features,
    const float* __restrict__ W0, const float* __restrict__ b0,
    const float* __restrict__ W1, const float* __restrict__ b1,
    const float* __restrict__ ln0g, const float* __restrict__ ln0b,
    const float* __restrict__ ln1g, const float* __restrict__ ln1b,
    float* __restrict__ out)
{
    __shared__ float An[Nn*PADB];   // 380
    __shared__ float XC[Nn*80];     // concat(x, pe); later reused as P1 (19x64)
    __shared__ float Z0[Nn*64];
    __shared__ float Z1[Nn*64];
    __shared__ float RS_s[4][Nn];   // per-warp partial sums
    __shared__ float RS_q[4][Nn];   // per-warp partial sum-of-squares

    const int g = blockIdx.x;
    const int b = g >> 10;
    const int t = g & 1023;
    const int tid = threadIdx.x;
    const int wid = tid >> 5;
    const int lane = tid & 31;

    // load a_norm
    {
        const float* ga = g_anorm + (size_t)g*Nn*Nn;
        for (int i = tid; i < Nn*Nn; i += 128)
            An[(i/Nn)*PADB + (i%Nn)] = ga[i];
    }
    // load x: XC[n][0:64] = features[b, n, t, :]
    for (int i = tid; i < Nn*64; i += 128){
        int n = i >> 6, dd = i & 63;
        XC[n*80 + dd] = features[((size_t)((b*Nn + n)*Tt + t))*64 + dd];
    }
    // load pe: XC[n][64:80]
    {
        const float* gp = g_pe + (size_t)g*Nn*KE;
        for (int i = tid; i < Nn*KE; i += 128){
            int n = i / KE, m = i % KE;
            XC[n*80 + 64 + m] = gp[i];
        }
    }
    __syncthreads();

    const int d    = tid & 63;
    const int half = tid >> 6;
    const int n0 = half ? 10 : 0;
    const int n1 = half ? 19 : 10;
    const int wbase = half*2;

    // ---- GEMM0: Z0 = XC @ W0^T   (W0 is (64,80) row-major) ----
    {
        float wreg[80];
        #pragma unroll
        for (int f4 = 0; f4 < 20; f4++){
            float4 v = *reinterpret_cast<const float4*>(W0 + d*80 + f4*4);
            wreg[f4*4+0] = v.x; wreg[f4*4+1] = v.y;
            wreg[f4*4+2] = v.z; wreg[f4*4+3] = v.w;
        }
        for (int n = n0; n < n1; n++){
            const float4* xr = reinterpret_cast<const float4*>(XC + n*80);
            float acc = 0.0f;
            #pragma unroll
            for (int f4 = 0; f4 < 20; f4++){
                float4 x = xr[f4];
                acc += x.x*wreg[f4*4+0] + x.y*wreg[f4*4+1]
                     + x.z*wreg[f4*4+2] + x.w*wreg[f4*4+3];
            }
            Z0[n*64 + d] = acc;
        }
    }
    __syncthreads();

    // ---- hop1: Z1 = A^T Z0 ----
    {
        float zc[Nn];
        #pragma unroll
        for (int i = 0; i < Nn; i++) zc[i] = Z0[i*64 + d];
        for (int n = n0; n < n1; n++){
            float acc = 0.0f;
            #pragma unroll
            for (int i = 0; i < Nn; i++) acc += An[i*PADB + n]*zc[i];
            Z1[n*64 + d] = acc;
        }
    }
    __syncthreads();

    // ---- y0 = alpha*Z0 + C*(Z1 + A^T Z1) + b0  -> Z0 ----
    {
        float zc[Nn];
        #pragma unroll
        for (int i = 0; i < Nn; i++) zc[i] = Z1[i*64 + d];
        float bb = b0[d];
        for (int n = n0; n < n1; n++){
            float acc = 0.0f;
            #pragma unroll
            for (int i = 0; i < Nn; i++) acc += An[i*PADB + n]*zc[i];
            Z0[n*64 + d] = ALPHA_C*Z0[n*64 + d] + HOPC*(Z1[n*64 + d] + acc) + bb;
        }
    }
    __syncthreads();

    // ---- LN0 stats: shfl butterfly over d within each warp, 2-warp combine ----
    for (int n = n0; n < n1; n++){
        float v = Z0[n*64 + d];                 // stride-1 across lanes: conflict-free
        float s = v, q = v*v;
        #pragma unroll
        for (int off = 16; off >= 1; off >>= 1){
            s += __shfl_xor_sync(0xffffffffu, s, off);
            q += __shfl_xor_sync(0xffffffffu, q, off);
        }
        if (lane == 0){ RS_s[wid][n] = s; RS_q[wid][n] = q; }
    }
    __syncthreads();
    {
        float gg = ln0g[d], bbb = ln0b[d];
        for (int n = n0; n < n1; n++){
            float s = RS_s[wbase][n] + RS_s[wbase+1][n];
            float q = RS_q[wbase][n] + RS_q[wbase+1][n];
            float mu = s * (1.0f/64.0f);
            float var = q * (1.0f/64.0f) - mu*mu;
            float rs = rsqrtf(fmaxf(var, 0.0f) + LN_EPS);
            Z0[n*64 + d] = (Z0[n*64 + d] - mu)*rs*gg + bbb;
        }
    }
    __syncthreads();

    // ---- GEMM1: Z1 = Z0 @ W1^T   (W1 is (64,64)) ----
    {
        float wreg[64];
        #pragma unroll
        for (int f4 = 0; f4 < 16; f4++){
            float4 v = *reinterpret_cast<const float4*>(W1 + d*64 + f4*4);
            wreg[f4*4+0] = v.x; wreg[f4*4+1] = v.y;
            wreg[f4*4+2] = v.z; wreg[f4*4+3] = v.w;
        }
        for (int n = n0; n < n1; n++){
            const float4* xr = reinterpret_cast<const float4*>(Z0 + n*64);
            float acc = 0.0f;
            #pragma unroll
            for (int f4 = 0; f4 < 16; f4++){
                float4 x = xr[f4];
                acc += x.x*wreg[f4*4+0] + x.y*wreg[f4*4+1]
                     + x.z*wreg[f4*4+2] + x.w*wreg[f4*4+3];
            }
            Z1[n*64 + d] = acc;
        }
    }
    __syncthreads();

    // ---- hop1: P1 (=XC region) = A^T Z1 ----
    {
        float zc[Nn];
        #pragma unroll
        for (int i = 0; i < Nn; i++) zc[i] = Z1[i*64 + d];
        for (int n = n0; n < n1; n++){
            float acc = 0.0f;
            #pragma unroll
            for (int i = 0; i < Nn; i++) acc += An[i*PADB + n]*zc[i];
            XC[n*64 + d] = acc;
        }
    }
    __syncthreads();

    // ---- y1 = alpha*Z1 + C*(P1 + A^T P1) + b1 + h0(Z0)  -> Z1 ----
    {
        float zc[Nn];
        #pragma unroll
        for (int i = 0; i < Nn; i++) zc[i] = XC[i*64 + d];
        float bb = b1[d];
        for (int n = n0; n < n1; n++){
            float acc = 0.0f;
            #pragma unroll
            for (int i = 0; i < Nn; i++) acc += An[i*PADB + n]*zc[i];
            Z1[n*64 + d] = ALPHA_C*Z1[n*64 + d] + HOPC*(XC[n*64 + d] + acc)
                         + bb + Z0[n*64 + d];
        }
    }
    __syncthreads();

    // ---- LN1 stats (shfl) + store ----
    for (int n = n0; n < n1; n++){
        float v = Z1[n*64 + d];
        float s = v, q = v*v;
        #pragma unroll
        for (int off = 16; off >= 1; off >>= 1){
            s += __shfl_xor_sync(0xffffffffu, s, off);
            q += __shfl_xor_sync(0xffffffffu, q, off);
        }
        if (lane == 0){ RS_s[wid][n] = s; RS_q[wid][n] = q; }
    }
    __syncthreads();
    {
        float gg = ln1g[d], bbb = ln1b[d];
        for (int n = n0; n < n1; n++){
            float s = RS_s[wbase][n] + RS_s[wbase+1][n];
            float q = RS_q[wbase][n] + RS_q[wbase+1][n];
            float mu = s * (1.0f/64.0f);
            float var = q * (1.0f/64.0f) - mu*mu;
            float rs = rsqrtf(fmaxf(var, 0.0f) + LN_EPS);
            float v = (Z1[n*64 + d] - mu)*rs*gg + bbb;
            out[((size_t)((b*Nn + n)*Tt + t))*64 + d] = v;
        }
    }
}

// ---------------------------------------------------------------------------
extern "C" void kernel_launch(void* const* d_in, const int* in_sizes, int n_in,
                              void* d_out, int out_size)
{
    const float* features  = (const float*)d_in[0];
    const float* adjacency = (const float*)d_in[1];
    const float* edge_w    = (const float*)d_in[2];
    const float* edge_b    = (const float*)d_in[3];
    const float* gnn0_W    = (const float*)d_in[4];
    const float* gnn0_b    = (const float*)d_in[5];
    const float* gnn1_W    = (const float*)d_in[6];
    const float* gnn1_b    = (const float*)d_in[7];
    const float* ln0_g     = (const float*)d_in[8];
    const float* ln0_b     = (const float*)d_in[9];
    const float* ln1_g     = (const float*)d_in[10];
    const float* ln1_b     = (const float*)d_in[11];
    float* out = (float*)d_out;

    eig_kernel<<<Gg/8, 256>>>(adjacency, edge_w, edge_b);
    dense_kernel<<<Gg, 128>>>(features, gnn0_W, gnn0_b, gnn1_W, gnn1_b,
                              ln0_g, ln0_b, ln1_g, ln1_b, out);
}

// round 11
// speedup vs baseline: 1.1003x; 1.0646x over previous
#include <cuda_runtime.h>
#include <math.h>

#define Nn 19
#define PADA 21      // eig kernel pad (conflict-free: gcd(21,32)=1)
#define PADG 20      // Gt row pad in dense (5 float4 per row)
#define ZPAD 68      // Z row stride: 16B-aligned, 3-way max LN conflicts
#define KE 16
#define Dd 64
#define Tt 1024
#define Bb 16
#define Gg (Bb*Tt)   // 16384 graphs
#define NSWEEP 5
#define ALPHA_C 0.05f
#define HOPC 0.475f  // (1-alpha)/K
#define LN_EPS 1e-5f

// scratch (allocation-free rule: __device__ globals)
__device__ float g_G[(size_t)Gg*Nn*Nn];       // fused propagation operator G^T
__device__ float g_pe[(size_t)Gg*Nn*KE];      // ~19.9 MB

__device__ __forceinline__ float softplusf(float x){
    return fmaxf(x, 0.0f) + log1pf(expf(-fabsf(x)));
}

// ---------------------------------------------------------------------------
// Kernel A: per-graph (one warp each): a_norm -> G = aI + C*A + C*A^2 (stored
// transposed) + symmetrized Laplacian + Jacobi eigensolver + PE extraction.
// ---------------------------------------------------------------------------
__global__ void __launch_bounds__(256) eig_kernel(
    const float* __restrict__ adjacency,
    const float* __restrict__ edge_w_p,
    const float* __restrict__ edge_b_p)
{
    __shared__ float smem[8*(2*Nn*PADA + 96)];
    const int w = threadIdx.x >> 5;
    const int l = threadIdx.x & 31;
    const int g = blockIdx.x*8 + w;

    float* M   = smem + w*(2*Nn*PADA + 96);   // adj -> identity -> EVEC
    float* V   = M + Nn*PADA;                 // w -> a_norm -> lapS -> diag
    float* AUX = V + Nn*PADA;
    float* CS  = AUX;                         // 9 cosines
    float* SS  = AUX + 9;                     // 9 sines
    float* DIS = AUX + 18;                    // 19
    int*   ORD = (int*)(AUX + 40);            // 16
    float* SGN = AUX + 56;                    // 16

    const float ew = edge_w_p[0];
    const float eb = edge_b_p[0];
    const float* adj = adjacency + (size_t)g*Nn*Nn;

    for (int i = l; i < Nn*Nn; i += 32)
        M[(i/Nn)*PADA + (i%Nn)] = adj[i];
    __syncwarp();

    for (int i = l; i < Nn*Nn; i += 32){
        int r = i/Nn, c = i%Nn;
        float a = M[r*PADA + c];
        V[r*PADA + c] = (a > 0.0f) ? softplusf(a*ew + eb) : 0.0f;
    }
    __syncwarp();
    if (l < Nn){
        if (!(M[l*PADA + l] > 0.0f)) V[l*PADA + l] += 1.0f;
    }
    __syncwarp();

    if (l < Nn){
        float dsum = 0.0f;
        #pragma unroll
        for (int i = 0; i < Nn; i++) dsum += V[i*PADA + l];
        DIS[l] = (dsum > 0.0f) ? rsqrtf(fmaxf(dsum, 1e-30f)) : 0.0f;
    }
    __syncwarp();

    // a_norm in place: V = dis_r * V * dis_c
    for (int i = l; i < Nn*Nn; i += 32){
        int r = i/Nn, c = i%Nn;
        V[r*PADA + c] = DIS[r]*V[r*PADA + c]*DIS[c];
    }
    __syncwarp();

    // G^T to global: Gt[n,i] = a*(i==n) + C*(A[i,n] + (A^2)[i,n])
    {
        float* gG = g_G + (size_t)g*Nn*Nn;
        for (int e = l; e < Nn*Nn; e += 32){
            int n = e/Nn, i = e - n*Nn;
            float s = 0.0f;
            #pragma unroll
            for (int j = 0; j < Nn; j++) s += V[i*PADA + j]*V[j*PADA + n];
            float val = HOPC*(V[i*PADA + n] + s);
            if (i == n) val += ALPHA_C;
            gG[e] = val;
        }
    }
    __syncwarp();

    // PE normalization: deg = max(row sums of raw adj, 1e-6)
    if (l < Nn){
        float dsum = 0.0f;
        #pragma unroll
        for (int j = 0; j < Nn; j++) dsum += M[l*PADA + j];
        DIS[l] = rsqrtf(fmaxf(dsum, 1e-6f));
    }
    __syncwarp();

    for (int i = l; i < Nn*Nn; i += 32){
        int r = i/Nn, c = i%Nn;
        float an = 0.5f * DIS[r]*DIS[c] * (M[r*PADA + c] + M[c*PADA + r]);
        V[r*PADA + c] = ((r == c) ? (1.0f + 1e-5f) : 0.0f) - an;
    }
    __syncwarp();

    for (int i = l; i < Nn*Nn; i += 32){
        int r = i/Nn, c = i%Nn;
        M[r*PADA + c] = (r == c) ? 1.0f : 0.0f;
    }
    __syncwarp();

    // per-lane round-invariant task descriptors (offsets, not pointers)
    int  cOff[11];   // (m? M : V) row base, relative to M
    int  cK[11];
    bool cValid[11];
    #pragma unroll
    for (int it = 0; it < 11; ++it){
        int t0 = l + 32*it;
        cValid[it] = (t0 < 2*9*Nn);
        int tt = cValid[it] ? t0 : 0;
        int m = tt / (9*Nn);
        int u = tt % (9*Nn);
        cK[it]   = u / Nn + 1;
        cOff[it] = (m ? 0 : Nn*PADA) + (u % Nn)*PADA;
    }
    int  rK[6], rJ[6];
    bool rValid[6];
    #pragma unroll
    for (int it = 0; it < 6; ++it){
        int t0 = l + 32*it;
        rValid[it] = (t0 < 9*Nn);
        int tt = rValid[it] ? t0 : 0;
        rK[it] = tt / Nn + 1;
        rJ[it] = tt % Nn;
    }

    for (int sweep = 0; sweep < NSWEEP; ++sweep){
        for (int r = 0; r < Nn; r++){
            if (l >= 1 && l <= 9){
                int k = l;
                int p = r + k; if (p >= Nn) p -= Nn;
                int q = r - k; if (q < 0)  q += Nn;
                float app = V[p*PADA + p];
                float aqq = V[q*PADA + q];
                float apq = V[p*PADA + q];
                float c = 1.0f, s = 0.0f;
                if (fabsf(apq) > 1e-30f){
                    float tau = (aqq - app) / (2.0f*apq);
                    float t = 1.0f / (fabsf(tau) + sqrtf(1.0f + tau*tau));
                    if (tau < 0.0f) t = -t;
                    c = rsqrtf(1.0f + t*t);
                    s = t*c;
                }
                CS[k-1] = c; SS[k-1] = s;
            }
            __syncwarp();
            #pragma unroll
            for (int it = 0; it < 11; ++it){
                if (cValid[it]){
                    int k = cK[it];
                    int p = r + k; if (p >= Nn) p -= Nn;
                    int q = r - k; if (q < 0)  q += Nn;
                    float c = CS[k-1], s = SS[k-1];
                    float* base = M + cOff[it];
                    float vp = base[p];
                    float vq = base[q];
                    base[p] = c*vp - s*vq;
                    base[q] = s*vp + c*vq;
                }
            }
            __syncwarp();
            #pragma unroll
            for (int it = 0; it < 6; ++it){
                if (rValid[it]){
                    int k = rK[it], j = rJ[it];
                    int p = r + k; if (p >= Nn) p -= Nn;
                    int q = r - k; if (q < 0)  q += Nn;
                    float c = CS[k-1], s = SS[k-1];
                    float vp = V[p*PADA + j];
                    float vq = V[q*PADA + j];
                    V[p*PADA + j] = c*vp - s*vq;
                    V[q*PADA + j] = s*vp + c*vq;
                }
            }
            __syncwarp();
        }
    }

    if (l < Nn){
        float dv = V[l*PADA + l];
        int rank = 0;
        #pragma unroll
        for (int j = 0; j < Nn; j++){
            float dj = V[j*PADA + j];
            rank += (dj < dv) || (dj == dv && j < l);
        }
        if (rank < KE) ORD[rank] = l;
    }
    __syncwarp();
    if (l < KE){
        int i = ORD[l];
        float sum = 0.0f;
        #pragma unroll
        for (int n = 0; n < Nn; n++) sum += M[n*PADA + i];
        SGN[l] = (sum > 0.0f) ? 1.0f : ((sum < 0.0f) ? -1.0f : 1.0f);
    }
    __syncwarp();
    {
        float* gp = g_pe + (size_t)g*Nn*KE;
        for (int t0 = l; t0 < Nn*KE; t0 += 32){
            int n = t0 / KE, m = t0 % KE;
            float v = M[n*PADA + ORD[m]] * SGN[m];
            if (isnan(v)) v = 0.0f;
            else if (isinf(v)) v = (v > 0.0f) ? 1.0f : -1.0f;
            gp[t0] = v;
        }
    }
}

// ---------------------------------------------------------------------------
// Kernel B: CTA-per-graph fused SSGConv0 -> LN0 -> SSGConv1 + res -> LN1.
// Propagation folded into one matrix: h = G^T z (single hop per conv),
// G rows read as 5x LDS.128 broadcasts. Z buffers stride-68 (3-way max
// conflicts in R7-style LN stat loops). Thread: half = tid/64, d = tid%64.
// ---------------------------------------------------------------------------
__global__ void __launch_bounds__(128) dense_kernel(
    const float* __restrict__ features,
    const float* __restrict__ W0, const float* __restrict__ b0,
    const float* __restrict__ W1, const float* __restrict__ b1,
    const float* __restrict__ ln0g, const float* __restrict__ ln0b,
    const float* __restrict__ ln1g, const float* __restrict__ ln1b,
    float* __restrict__ out)
{
    __shared__ __align__(16) float Gt[Nn*PADG];   // 380 (col 19 zeroed)
    __shared__ __align__(16) float XC[Nn*80];     // x|pe; reused as h1 (19xZPAD)
    __shared__ __align__(16) float Z0[Nn*ZPAD];
    __shared__ __align__(16) float Z1[Nn*ZPAD];
    __shared__ float MU[Nn], RS[Nn];

    const int g = blockIdx.x;
    const int b = g >> 10;
    const int t = g & 1023;
    const int tid = threadIdx.x;

    // load G^T (pad col to 0)
    {
        const float* gG = g_G + (size_t)g*Nn*Nn;
        for (int e = tid; e < Nn*Nn; e += 128)
            Gt[(e/Nn)*PADG + (e%Nn)] = gG[e];
        if (tid < Nn) Gt[tid*PADG + Nn] = 0.0f;
    }
    // load x: XC[n][0:64] = features[b, n, t, :]
    for (int i = tid; i < Nn*64; i += 128){
        int n = i >> 6, dd = i & 63;
        XC[n*80 + dd] = features[((size_t)((b*Nn + n)*Tt + t))*64 + dd];
    }
    // load pe: XC[n][64:80]
    {
        const float* gp = g_pe + (size_t)g*Nn*KE;
        for (int i = tid; i < Nn*KE; i += 128){
            int n = i / KE, m = i % KE;
            XC[n*80 + 64 + m] = gp[i];
        }
    }
    __syncthreads();

    const int d    = tid & 63;
    const int half = tid >> 6;
    const int n0 = half ? 10 : 0;
    const int n1 = half ? 19 : 10;

    // ---- GEMM0: Z0 = XC @ W0^T   (W0 is (64,80) row-major) ----
    {
        float wreg[80];
        #pragma unroll
        for (int f4 = 0; f4 < 20; f4++){
            float4 v = *reinterpret_cast<const float4*>(W0 + d*80 + f4*4);
            wreg[f4*4+0] = v.x; wreg[f4*4+1] = v.y;
            wreg[f4*4+2] = v.z; wreg[f4*4+3] = v.w;
        }
        for (int n = n0; n < n1; n++){
            const float4* xr = reinterpret_cast<const float4*>(XC + n*80);
            float acc = 0.0f;
            #pragma unroll
            for (int f4 = 0; f4 < 20; f4++){
                float4 x = xr[f4];
                acc += x.x*wreg[f4*4+0] + x.y*wreg[f4*4+1]
                     + x.z*wreg[f4*4+2] + x.w*wreg[f4*4+3];
            }
            Z0[n*ZPAD + d] = acc;
        }
    }
    __syncthreads();

    // ---- prop0: Z1 = G^T Z0 + b0 ----
    {
        float zc[20];
        #pragma unroll
        for (int i = 0; i < Nn; i++) zc[i] = Z0[i*ZPAD + d];
        zc[19] = 0.0f;
        float bb = b0[d];
        for (int n = n0; n < n1; n++){
            const float4* gr = reinterpret_cast<const float4*>(Gt + n*PADG);
            float4 g0 = gr[0], g1 = gr[1], g2 = gr[2], g3 = gr[3], g4 = gr[4];
            float acc =
                g0.x*zc[0]  + g0.y*zc[1]  + g0.z*zc[2]  + g0.w*zc[3]
              + g1.x*zc[4]  + g1.y*zc[5]  + g1.z*zc[6]  + g1.w*zc[7]
              + g2.x*zc[8]  + g2.y*zc[9]  + g2.z*zc[10] + g2.w*zc[11]
              + g3.x*zc[12] + g3.y*zc[13] + g3.z*zc[14] + g3.w*zc[15]
              + g4.x*zc[16] + g4.y*zc[17] + g4.z*zc[18] + g4.w*zc[19];
            Z1[n*ZPAD + d] = acc + bb;
        }
    }
    __syncthreads();

    // ---- LN0 stats on Z1 (R7 style; stride-68 -> 3-way conflicts max) ----
    if (tid < Nn){
        float mu = 0.0f;
        #pragma unroll
        for (int j = 0; j < 64; j++) mu += Z1[tid*ZPAD + j];
        mu *= (1.0f/64.0f);
        float var = 0.0f;
        #pragma unroll
        for (int j = 0; j < 64; j++){ float dv = Z1[tid*ZPAD + j] - mu; var += dv*dv; }
        var *= (1.0f/64.0f);
        MU[tid] = mu; RS[tid] = rsqrtf(var + LN_EPS);
    }
    __syncthreads();
    // LN0 apply -> Z0 (GEMM1 input AND residual)
    {
        float gg = ln0g[d], bbb = ln0b[d];
        for (int n = n0; n < n1; n++)
            Z0[n*ZPAD + d] = (Z1[n*ZPAD + d] - MU[n])*RS[n]*gg + bbb;
    }
    __syncthreads();

    // ---- GEMM1: Z1 = Z0 @ W1^T   (W1 is (64,64)) ----
    {
        float wreg[64];
        #pragma unroll
        for (int f4 = 0; f4 < 16; f4++){
            float4 v = *reinterpret_cast<const float4*>(W1 + d*64 + f4*4);
            wreg[f4*4+0] = v.x; wreg[f4*4+1] = v.y;
            wreg[f4*4+2] = v.z; wreg[f4*4+3] = v.w;
        }
        for (int n = n0; n < n1; n++){
            const float4* xr = reinterpret_cast<const float4*>(Z0 + n*ZPAD);
            float acc = 0.0f;
            #pragma unroll
            for (int f4 = 0; f4 < 16; f4++){
                float4 x = xr[f4];
                acc += x.x*wreg[f4*4+0] + x.y*wreg[f4*4+1]
                     + x.z*wreg[f4*4+2] + x.w*wreg[f4*4+3];
            }
            Z1[n*ZPAD + d] = acc;
        }
    }
    __syncthreads();

    // ---- prop1 + residual: h1 = G^T Z1 + b1 + Z0  -> XC (stride ZPAD) ----
    {
        float zc[20];
        #pragma unroll
        for (int i = 0; i < Nn; i++) zc[i] = Z1[i*ZPAD + d];
        zc[19] = 0.0f;
        float bb = b1[d];
        for (int n = n0; n < n1; n++){
            const float4* gr = reinterpret_cast<const float4*>(Gt + n*PADG);
            float4 g0 = gr[0], g1 = gr[1], g2 = gr[2], g3 = gr[3], g4 = gr[4];
            float acc =
                g0.x*zc[0]  + g0.y*zc[1]  + g0.z*zc[2]  + g0.w*zc[3]
              + g1.x*zc[4]  + g1.y*zc[5]  + g1.z*zc[6]  + g1.w*zc[7]
              + g2.x*zc[8]  + g2.y*zc[9]  + g2.z*zc[10] + g2.w*zc[11]
              + g3.x*zc[12] + g3.y*zc[13] + g3.z*zc[14] + g3.w*zc[15]
              + g4.x*zc[16] + g4.y*zc[17] + g4.z*zc[18] + g4.w*zc[19];
            XC[n*ZPAD + d] = acc + bb + Z0[n*ZPAD + d];
        }
    }
    __syncthreads();

    // ---- LN1 stats on XC ----
    if (tid < Nn){
        float mu = 0.0f;
        #pragma unroll
        for (int j = 0; j < 64; j++) mu += XC[tid*ZPAD + j];
        mu *= (1.0f/64.0f);
        float var = 0.0f;
        #pragma unroll
        for (int j = 0; j < 64; j++){ float dv = XC[tid*ZPAD + j] - mu; var += dv*dv; }
        var *= (1.0f/64.0f);
        MU[tid] = mu; RS[tid] = rsqrtf(var + LN_EPS);
    }
    __syncthreads();
    {
        float gg = ln1g[d], bbb = ln1b[d];
        for (int n = n0; n < n1; n++){
            float v = (XC[n*ZPAD + d] - MU[n])*RS[n]*gg + bbb;
            out[((size_t)((b*Nn + n)*Tt + t))*64 + d] = v;
        }
    }
}

// ---------------------------------------------------------------------------
extern "C" void kernel_launch(void* const* d_in, const int* in_sizes, int n_in,
                              void* d_out, int out_size)
{
    const float* features  = (const float*)d_in[0];
    const float* adjacency = (const float*)d_in[1];
    const float* edge_w    = (const float*)d_in[2];
    const float* edge_b    = (const float*)d_in[3];
    const float* gnn0_W    = (const float*)d_in[4];
    const float* gnn0_b    = (const float*)d_in[5];
    const float* gnn1_W    = (const float*)d_in[6];
    const float* gnn1_b    = (const float*)d_in[7];
    const float* ln0_g     = (const float*)d_in[8];
    const float* ln0_b     = (const float*)d_in[9];
    const float* ln1_g     = (const float*)d_in[10];
    const float* ln1_b     = (const float*)d_in[11];
    float* out = (float*)d_out;

    eig_kernel<<<Gg/8, 256>>>(adjacency, edge_w, edge_b);
    dense_kernel<<<Gg, 128>>>(features, gnn0_W, gnn0_b, gnn1_W, gnn1_b,
                              ln0_g, ln0_b, ln1_g, ln1_b, out);
}

// round 13
// speedup vs baseline: 1.1483x; 1.0436x over previous
#include <cuda_runtime.h>
#include <math.h>

#define Nn 19
#define PADA 21      // eig kernel pad (conflict-free: gcd(21,32)=1)
#define PADG 20      // Gt row pad in dense (5 float4 per row)
#define ZPAD 68      // Z row stride: 16B-aligned, 3-way max LN conflicts
#define PADW 81      // W stage pad: gcd(81,32)=1 -> conflict-free row reads
#define KE 16
#define Dd 64
#define Tt 1024
#define Bb 16
#define Gg (Bb*Tt)   // 16384 graphs
#define NSWEEP 5     // 4 sweeps FAILED accuracy (1.7e-3); 5 is the floor
#define ALPHA_C 0.05f
#define HOPC 0.475f  // (1-alpha)/K
#define LN_EPS 1e-5f

// scratch (allocation-free rule: __device__ globals)
__device__ float g_G[(size_t)Gg*Nn*Nn];       // fused propagation operator G^T
__device__ float g_pe[(size_t)Gg*Nn*KE];      // ~19.9 MB

__device__ __forceinline__ float softplusf(float x){
    return fmaxf(x, 0.0f) + log1pf(expf(-fabsf(x)));
}

// ---------------------------------------------------------------------------
// Kernel A: per-graph (one warp each): a_norm -> G = aI + C*A + C*A^2 (stored
// transposed) + symmetrized Laplacian + Jacobi eigensolver + PE extraction.
// ---------------------------------------------------------------------------
__global__ void __launch_bounds__(256) eig_kernel(
    const float* __restrict__ adjacency,
    const float* __restrict__ edge_w_p,
    const float* __restrict__ edge_b_p)
{
    __shared__ float smem[8*(2*Nn*PADA + 96)];
    const int w = threadIdx.x >> 5;
    const int l = threadIdx.x & 31;
    const int g = blockIdx.x*8 + w;

    float* M   = smem + w*(2*Nn*PADA + 96);   // adj -> identity -> EVEC
    float* V   = M + Nn*PADA;                 // w -> a_norm -> lapS -> diag
    float* AUX = V + Nn*PADA;
    float* CS  = AUX;                         // 9 cosines
    float* SS  = AUX + 9;                     // 9 sines
    float* DIS = AUX + 18;                    // 19
    int*   ORD = (int*)(AUX + 40);            // 16
    float* SGN = AUX + 56;                    // 16

    const float ew = edge_w_p[0];
    const float eb = edge_b_p[0];
    const float* adj = adjacency + (size_t)g*Nn*Nn;

    for (int i = l; i < Nn*Nn; i += 32)
        M[(i/Nn)*PADA + (i%Nn)] = adj[i];
    __syncwarp();

    for (int i = l; i < Nn*Nn; i += 32){
        int r = i/Nn, c = i%Nn;
        float a = M[r*PADA + c];
        V[r*PADA + c] = (a > 0.0f) ? softplusf(a*ew + eb) : 0.0f;
    }
    __syncwarp();
    if (l < Nn){
        if (!(M[l*PADA + l] > 0.0f)) V[l*PADA + l] += 1.0f;
    }
    __syncwarp();

    if (l < Nn){
        float dsum = 0.0f;
        #pragma unroll
        for (int i = 0; i < Nn; i++) dsum += V[i*PADA + l];
        DIS[l] = (dsum > 0.0f) ? rsqrtf(fmaxf(dsum, 1e-30f)) : 0.0f;
    }
    __syncwarp();

    // a_norm in place: V = dis_r * V * dis_c
    for (int i = l; i < Nn*Nn; i += 32){
        int r = i/Nn, c = i%Nn;
        V[r*PADA + c] = DIS[r]*V[r*PADA + c]*DIS[c];
    }
    __syncwarp();

    // G^T to global: Gt[n,i] = a*(i==n) + C*(A[i,n] + (A^2)[i,n])
    {
        float* gG = g_G + (size_t)g*Nn*Nn;
        for (int e = l; e < Nn*Nn; e += 32){
            int n = e/Nn, i = e - n*Nn;
            float s = 0.0f;
            #pragma unroll
            for (int j = 0; j < Nn; j++) s += V[i*PADA + j]*V[j*PADA + n];
            float val = HOPC*(V[i*PADA + n] + s);
            if (i == n) val += ALPHA_C;
            gG[e] = val;
        }
    }
    __syncwarp();

    // PE normalization: deg = max(row sums of raw adj, 1e-6)
    if (l < Nn){
        float dsum = 0.0f;
        #pragma unroll
        for (int j = 0; j < Nn; j++) dsum += M[l*PADA + j];
        DIS[l] = rsqrtf(fmaxf(dsum, 1e-6f));
    }
    __syncwarp();

    for (int i = l; i < Nn*Nn; i += 32){
        int r = i/Nn, c = i%Nn;
        float an = 0.5f * DIS[r]*DIS[c] * (M[r*PADA + c] + M[c*PADA + r]);
        V[r*PADA + c] = ((r == c) ? (1.0f + 1e-5f) : 0.0f) - an;
    }
    __syncwarp();

    for (int i = l; i < Nn*Nn; i += 32){
        int r = i/Nn, c = i%Nn;
        M[r*PADA + c] = (r == c) ? 1.0f : 0.0f;
    }
    __syncwarp();

    // per-lane round-invariant task descriptors (offsets, not pointers)
    int  cOff[11];   // (m? M : V) row base, relative to M
    int  cK[11];
    bool cValid[11];
    #pragma unroll
    for (int it = 0; it < 11; ++it){
        int t0 = l + 32*it;
        cValid[it] = (t0 < 2*9*Nn);
        int tt = cValid[it] ? t0 : 0;
        int m = tt / (9*Nn);
        int u = tt % (9*Nn);
        cK[it]   = u / Nn + 1;
        cOff[it] = (m ? 0 : Nn*PADA) + (u % Nn)*PADA;
    }
    int  rK[6], rJ[6];
    bool rValid[6];
    #pragma unroll
    for (int it = 0; it < 6; ++it){
        int t0 = l + 32*it;
        rValid[it] = (t0 < 9*Nn);
        int tt = rValid[it] ? t0 : 0;
        rK[it] = tt / Nn + 1;
        rJ[it] = tt % Nn;
    }

    for (int sweep = 0; sweep < NSWEEP; ++sweep){
        for (int r = 0; r < Nn; r++){
            if (l >= 1 && l <= 9){
                int k = l;
                int p = r + k; if (p >= Nn) p -= Nn;
                int q = r - k; if (q < 0)  q += Nn;
                float app = V[p*PADA + p];
                float aqq = V[q*PADA + q];
                float apq = V[p*PADA + q];
                float c = 1.0f, s = 0.0f;
                if (fabsf(apq) > 1e-30f){
                    float tau = (aqq - app) / (2.0f*apq);
                    float t = 1.0f / (fabsf(tau) + sqrtf(1.0f + tau*tau));
                    if (tau < 0.0f) t = -t;
                    c = rsqrtf(1.0f + t*t);
                    s = t*c;
                }
                CS[k-1] = c; SS[k-1] = s;
            }
            __syncwarp();
            #pragma unroll
            for (int it = 0; it < 11; ++it){
                if (cValid[it]){
                    int k = cK[it];
                    int p = r + k; if (p >= Nn) p -= Nn;
                    int q = r - k; if (q < 0)  q += Nn;
                    float c = CS[k-1], s = SS[k-1];
                    float* base = M + cOff[it];
                    float vp = base[p];
                    float vq = base[q];
                    base[p] = c*vp - s*vq;
                    base[q] = s*vp + c*vq;
                }
            }
            __syncwarp();
            #pragma unroll
            for (int it = 0; it < 6; ++it){
                if (rValid[it]){
                    int k = rK[it], j = rJ[it];
                    int p = r + k; if (p >= Nn) p -= Nn;
                    int q = r - k; if (q < 0)  q += Nn;
                    float c = CS[k-1], s = SS[k-1];
                    float vp = V[p*PADA + j];
                    float vq = V[q*PADA + j];
                    V[p*PADA + j] = c*vp - s*vq;
                    V[q*PADA + j] = s*vp + c*vq;
                }
            }
            __syncwarp();
        }
    }

    if (l < Nn){
        float dv = V[l*PADA + l];
        int rank = 0;
        #pragma unroll
        for (int j = 0; j < Nn; j++){
            float dj = V[j*PADA + j];
            rank += (dj < dv) || (dj == dv && j < l);
        }
        if (rank < KE) ORD[rank] = l;
    }
    __syncwarp();
    if (l < KE){
        int i = ORD[l];
        float sum = 0.0f;
        #pragma unroll
        for (int n = 0; n < Nn; n++) sum += M[n*PADA + i];
        SGN[l] = (sum > 0.0f) ? 1.0f : ((sum < 0.0f) ? -1.0f : 1.0f);
    }
    __syncwarp();
    {
        float* gp = g_pe + (size_t)g*Nn*KE;
        for (int t0 = l; t0 < Nn*KE; t0 += 32){
            int n = t0 / KE, m = t0 % KE;
            float v = M[n*PADA + ORD[m]] * SGN[m];
            if (isnan(v)) v = 0.0f;
            else if (isinf(v)) v = (v > 0.0f) ? 1.0f : -1.0f;
            gp[t0] = v;
        }
    }
}

// ---------------------------------------------------------------------------
// Kernel B: CTA-per-graph fused SSGConv0 -> LN0 -> SSGConv1 + res -> LN1.
// Weights staged in shared (coalesced LDG; pad 81 -> conflict-free LDS fill)
// instead of 32-line-per-request strided LDG.128 gathers. Propagation via
// fused G^T. Thread: half = tid/64, d = tid%64.
// ---------------------------------------------------------------------------
__global__ void __launch_bounds__(128) dense_kernel(
    const float* __restrict__ features,
    const float* __restrict__ W0, const float* __restrict__ b0,
    const float* __restrict__ W1, const float* __restrict__ b1,
    const float* __restrict__ ln0g, const float* __restrict__ ln0b,
    const float* __restrict__ ln1g, const float* __restrict__ ln1b,
    float* __restrict__ out)
{
    __shared__ __align__(16) float Gt[Nn*PADG];   // 380 (col 19 zeroed)
    __shared__ __align__(16) float XC[Nn*80];     // x|pe; reused as h1 (19xZPAD)
    __shared__ __align__(16) float Z0[Nn*ZPAD];
    __shared__ __align__(16) float Z1[Nn*ZPAD];
    __shared__ __align__(16) float SW[64*PADW];   // staged weights (W0, then W1)
    __shared__ float MU[Nn], RS[Nn];

    const int g = blockIdx.x;
    const int b = g >> 10;
    const int t = g & 1023;
    const int tid = threadIdx.x;

    // load G^T (pad col to 0)
    {
        const float* gG = g_G + (size_t)g*Nn*Nn;
        for (int e = tid; e < Nn*Nn; e += 128)
            Gt[(e/Nn)*PADG + (e%Nn)] = gG[e];
        if (tid < Nn) Gt[tid*PADG + Nn] = 0.0f;
    }
    // stage W0 (64x80) coalesced into SW rows of stride 81
    for (int i = tid; i < 64*80; i += 128){
        int r = i / 80, c = i - r*80;
        SW[r*PADW + c] = W0[i];
    }
    // load x: XC[n][0:64] = features[b, n, t, :]
    for (int i = tid; i < Nn*64; i += 128){
        int n = i >> 6, dd = i & 63;
        XC[n*80 + dd] = features[((size_t)((b*Nn + n)*Tt + t))*64 + dd];
    }
    // load pe: XC[n][64:80]
    {
        const float* gp = g_pe + (size_t)g*Nn*KE;
        for (int i = tid; i < Nn*KE; i += 128){
            int n = i / KE, m = i % KE;
            XC[n*80 + 64 + m] = gp[i];
        }
    }
    __syncthreads();

    const int d    = tid & 63;
    const int half = tid >> 6;
    const int n0 = half ? 10 : 0;
    const int n1 = half ? 19 : 10;

    // ---- GEMM0: Z0 = XC @ W0^T  (wreg filled from smem, conflict-free) ----
    {
        float wreg[80];
        #pragma unroll
        for (int j = 0; j < 80; j++) wreg[j] = SW[d*PADW + j];
        for (int n = n0; n < n1; n++){
            const float4* xr = reinterpret_cast<const float4*>(XC + n*80);
            float acc = 0.0f;
            #pragma unroll
            for (int f4 = 0; f4 < 20; f4++){
                float4 x = xr[f4];
                acc += x.x*wreg[f4*4+0] + x.y*wreg[f4*4+1]
                     + x.z*wreg[f4*4+2] + x.w*wreg[f4*4+3];
            }
            Z0[n*ZPAD + d] = acc;
        }
    }
    __syncthreads();

    // stage W1 (64x64) into SW (overwrites W0; all threads passed the sync
    // above, and consumers re-read only after the LN0 __syncthreads below)
    for (int i = tid; i < 64*64; i += 128){
        int r = i >> 6, c = i & 63;
        SW[r*PADW + c] = W1[i];
    }

    // ---- prop0: Z1 = G^T Z0 + b0 ----
    {
        float zc[20];
        #pragma unroll
        for (int i = 0; i < Nn; i++) zc[i] = Z0[i*ZPAD + d];
        zc[19] = 0.0f;
        float bb = b0[d];
        for (int n = n0; n < n1; n++){
            const float4* gr = reinterpret_cast<const float4*>(Gt + n*PADG);
            float4 g0 = gr[0], g1 = gr[1], g2 = gr[2], g3 = gr[3], g4 = gr[4];
            float acc =
                g0.x*zc[0]  + g0.y*zc[1]  + g0.z*zc[2]  + g0.w*zc[3]
              + g1.x*zc[4]  + g1.y*zc[5]  + g1.z*zc[6]  + g1.w*zc[7]
              + g2.x*zc[8]  + g2.y*zc[9]  + g2.z*zc[10] + g2.w*zc[11]
              + g3.x*zc[12] + g3.y*zc[13] + g3.z*zc[14] + g3.w*zc[15]
              + g4.x*zc[16] + g4.y*zc[17] + g4.z*zc[18] + g4.w*zc[19];
            Z1[n*ZPAD + d] = acc + bb;
        }
    }
    __syncthreads();

    // ---- LN0 stats on Z1 (stride-68 -> 3-way conflicts max) ----
    if (tid < Nn){
        float mu = 0.0f;
        #pragma unroll
        for (int j = 0; j < 64; j++) mu += Z1[tid*ZPAD + j];
        mu *= (1.0f/64.0f);
        float var = 0.0f;
        #pragma unroll
        for (int j = 0; j < 64; j++){ float dv = Z1[tid*ZPAD + j] - mu; var += dv*dv; }
        var *= (1.0f/64.0f);
        MU[tid] = mu; RS[tid] = rsqrtf(var + LN_EPS);
    }
    __syncthreads();
    // LN0 apply -> Z0 (GEMM1 input AND residual)
    {
        float gg = ln0g[d], bbb = ln0b[d];
        for (int n = n0; n < n1; n++)
            Z0[n*ZPAD + d] = (Z1[n*ZPAD + d] - MU[n])*RS[n]*gg + bbb;
    }
    __syncthreads();

    // ---- GEMM1: Z1 = Z0 @ W1^T  (wreg from smem) ----
    {
        float wreg[64];
        #pragma unroll
        for (int j = 0; j < 64; j++) wreg[j] = SW[d*PADW + j];
        for (int n = n0; n < n1; n++){
            const float4* xr = reinterpret_cast<const float4*>(Z0 + n*ZPAD);
            float acc = 0.0f;
            #pragma unroll
            for (int f4 = 0; f4 < 16; f4++){
                float4 x = xr[f4];
                acc += x.x*wreg[f4*4+0] + x.y*wreg[f4*4+1]
                     + x.z*wreg[f4*4+2] + x.w*wreg[f4*4+3];
            }
            Z1[n*ZPAD + d] = acc;
        }
    }
    __syncthreads();

    // ---- prop1 + residual: h1 = G^T Z1 + b1 + Z0  -> XC (stride ZPAD) ----
    {
        float zc[20];
        #pragma unroll
        for (int i = 0; i < Nn; i++) zc[i] = Z1[i*ZPAD + d];
        zc[19] = 0.0f;
        float bb = b1[d];
        for (int n = n0; n < n1; n++){
            const float4* gr = reinterpret_cast<const float4*>(Gt + n*PADG);
            float4 g0 = gr[0], g1 = gr[1], g2 = gr[2], g3 = gr[3], g4 = gr[4];
            float acc =
                g0.x*zc[0]  + g0.y*zc[1]  + g0.z*zc[2]  + g0.w*zc[3]
              + g1.x*zc[4]  + g1.y*zc[5]  + g1.z*zc[6]  + g1.w*zc[7]
              + g2.x*zc[8]  + g2.y*zc[9]  + g2.z*zc[10] + g2.w*zc[11]
              + g3.x*zc[12] + g3.y*zc[13] + g3.z*zc[14] + g3.w*zc[15]
              + g4.x*zc[16] + g4.y*zc[17] + g4.z*zc[18] + g4.w*zc[19];
            XC[n*ZPAD + d] = acc + bb + Z0[n*ZPAD + d];
        }
    }
    __syncthreads();

    // ---- LN1 stats on XC ----
    if (tid < Nn){
        float mu = 0.0f;
        #pragma unroll
        for (int j = 0; j < 64; j++) mu += XC[tid*ZPAD + j];
        mu *= (1.0f/64.0f);
        float var = 0.0f;
        #pragma unroll
        for (int j = 0; j < 64; j++){ float dv = XC[tid*ZPAD + j] - mu; var += dv*dv; }
        var *= (1.0f/64.0f);
        MU[tid] = mu; RS[tid] = rsqrtf(var + LN_EPS);
    }
    __syncthreads();
    {
        float gg = ln1g[d], bbb = ln1b[d];
        for (int n = n0; n < n1; n++){
            float v = (XC[n*ZPAD + d] - MU[n])*RS[n]*gg + bbb;
            out[((size_t)((b*Nn + n)*Tt + t))*64 + d] = v;
        }
    }
}

// ---------------------------------------------------------------------------
extern "C" void kernel_launch(void* const* d_in, const int* in_sizes, int n_in,
                              void* d_out, int out_size)
{
    const float* features  = (const float*)d_in[0];
    const float* adjacency = (const float*)d_in[1];
    const float* edge_w    = (const float*)d_in[2];
    const float* edge_b    = (const float*)d_in[3];
    const float* gnn0_W    = (const float*)d_in[4];
    const float* gnn0_b    = (const float*)d_in[5];
    const float* gnn1_W    = (const float*)d_in[6];
    const float* gnn1_b    = (const float*)d_in[7];
    const float* ln0_g     = (const float*)d_in[8];
    const float* ln0_b     = (const float*)d_in[9];
    const float* ln1_g     = (const float*)d_in[10];
    const float* ln1_b     = (const float*)d_in[11];
    float* out = (float*)d_out;

    eig_kernel<<<Gg/8, 256>>>(adjacency, edge_w, edge_b);
    dense_kernel<<<Gg, 128>>>(features, gnn0_W, gnn0_b, gnn1_W, gnn1_b,
                              ln0_g, ln0_b, ln1_g, ln1_b, out);
}